// round 14
// baseline (speedup 1.0000x reference)
#include <cuda_runtime.h>

// Pyramid Givens circuit, n = m = 512, B = 256.
// Layer t in [0,1021): gates (i,i+1) for i ≡ t (mod 2), 0 <= i <= min(t, 1020-t).
// theta index: q=(t+i)/2, tidx = q(q+1)/2 + q - i.  Gate: a'=c*a+s*b ; b'=c*b-s*a.
//
// Lane L owns wires [8L,8L+7] (h=0) and [256+8L,256+8L+7] (h=1), packed as
// (v_{w+k}, v_{w+k+4}). Upper half active only for t in [255,765]; chunks
// (20 layers) phase-split into both-halves / lower-only straight-line bodies.
// Negated sines precomputed in the table (no per-stage XORs). All smem loads:
// 32-bit shared base + compile-time immediate.

#define N_WIRES   512
#define CHUNK_L   20
#define NCHUNK    52                   // 52*20 = 1040 layers (tail identity)
#define T_PAD     (NCHUNK * CHUNK_L)   // 1040
#define LAYER_B   3584                 // rot cs 2048 + ns 1024 + left 512
#define NS_OFF    2048
#define LEFT_OFF  3072
#define CHUNK_B   (CHUNK_L * LAYER_B)  // 71680
#define STAGE_B   (2 * LAYER_B)        // 7168
#define MID_LO    12                   // chunks 12..38 cover t in [240,779] ⊇ [255,765]
#define MID_HI    38

typedef unsigned long long ull;

// Per layer t (stride LAYER_B):
//   [0,2048):      rot double2 {c2,s2}, entry at h*1024 + r*512 + lane*16
//   [2048,3072):   ns2 pairs [nEs_r0, nEs_r1], entry at h*512 + lane*16 (r*8 within)
//   [3072,3584):   left-gate float2 (c, -s), entry at h*256 + lane*8
// Inactive gates stored as identity.
__device__ __align__(128) char g_tab[(size_t)T_PAD * LAYER_B];   // ~3.7 MB

__device__ __forceinline__ float2 cs_of(const float* __restrict__ th, int t, int i) {
    if (t <= 1020 && i >= 0 && i <= t && i <= 1020 - t && (((i ^ t) & 1) == 0)) {
        int q = (t + i) >> 1;
        int tidx = (q * (q + 1)) / 2 + q - i;
        float s, c;
        __sincosf(th[tidx], &s, &c);    // |theta| <= pi
        return make_float2(c, s);
    }
    return make_float2(1.0f, 0.0f);
}

// 512 threads = 4 layers per block.
__global__ void build_cs_kernel(const float* __restrict__ thetas) {
    int t    = blockIdx.x * 4 + (threadIdx.x >> 7);
    if (t >= T_PAD) return;
    int h    = (threadIdx.x >> 6) & 1;
    int r    = (threadIdx.x >> 5) & 1;
    int lane = threadIdx.x & 31;
    int w    = 256 * h + 8 * lane;
    int ilo, ihi;
    if ((t & 1) == 0) { ilo = w + 2 * r;     ihi = ilo + 4; }
    else              { ilo = w + 2 * r + 1; ihi = ilo + 4; }
    float2 a = cs_of(thetas, t, ilo);
    float2 b = cs_of(thetas, t, ihi);
    char* base = g_tab + (size_t)t * LAYER_B;
    float2* dst = reinterpret_cast<float2*>(base + h * 1024 + r * 512 + lane * 16);
    dst[0] = make_float2(a.x, b.x);   // c2
    dst[1] = make_float2(a.y, b.y);   // s2
    // negated sine pair
    *reinterpret_cast<float2*>(base + NS_OFF + h * 512 + lane * 16 + r * 8)
        = make_float2(-a.y, -b.y);
    if (r == 0) {
        float2 lf = cs_of(thetas, t, w - 1);
        *reinterpret_cast<float2*>(base + LEFT_OFF + h * 256 + lane * 8)
            = make_float2(lf.x, -lf.y);        // sine pre-negated
    }
}

// ---- f32x2 helpers ----
__device__ __forceinline__ ull mul2(ull a, ull b) {
    ull d; asm("mul.rn.f32x2 %0, %1, %2;" : "=l"(d) : "l"(a), "l"(b)); return d;
}
__device__ __forceinline__ ull fma2(ull a, ull b, ull c) {
    ull d; asm("fma.rn.f32x2 %0, %1, %2, %3;" : "=l"(d) : "l"(a), "l"(b), "l"(c)); return d;
}
__device__ __forceinline__ float lo_f(ull p) {
    float lo; asm("{ .reg .b32 hi_; mov.b64 {%0, hi_}, %1; }" : "=f"(lo) : "l"(p)); return lo;
}
__device__ __forceinline__ float hi_f(ull p) {
    float hi; asm("{ .reg .b32 lo_; mov.b64 {lo_, %0}, %1; }" : "=f"(hi) : "l"(p)); return hi;
}
__device__ __forceinline__ ull pk(float lo, float hi) {
    ull d; asm("mov.b64 %0, {%1, %2};" : "=l"(d) : "f"(lo), "f"(hi)); return d;
}

#define FULLM 0xffffffffu

__device__ __forceinline__ void rotp2(ull& a, ull& b, ull c2, ull s2, ull ns2) {
    ull t1 = mul2(s2, b);
    ull na = fma2(c2, a, t1);
    ull t2 = mul2(ns2, a);
    b = fma2(c2, b, t2);
    a = na;
}

// ---- 32-bit shared loads with immediate offsets ----
template<int OFF>
__device__ __forceinline__ void lds_u64x2(unsigned base, ull& x, ull& y) {
    asm volatile("ld.shared.v2.u64 {%0, %1}, [%2+%3];"
                 : "=l"(x), "=l"(y) : "r"(base), "n"(OFF));
}
template<int OFF>
__device__ __forceinline__ void lds_f32x2(unsigned base, float& x, float& y) {
    asm volatile("ld.shared.v2.f32 {%0, %1}, [%2+%3];"
                 : "=f"(x), "=f"(y) : "r"(base), "n"(OFF));
}

// ---- bulk-copy / mbarrier helpers ----
__device__ __forceinline__ unsigned s2u(const void* p) {
    return (unsigned)__cvta_generic_to_shared(p);
}
__device__ __forceinline__ void mbar_init(unsigned mbar, unsigned cnt) {
    asm volatile("mbarrier.init.shared.b64 [%0], %1;" :: "r"(mbar), "r"(cnt) : "memory");
}
__device__ __forceinline__ void mbar_expect_tx(unsigned mbar, unsigned bytes) {
    asm volatile("mbarrier.arrive.expect_tx.shared.b64 _, [%0], %1;"
                 :: "r"(mbar), "r"(bytes) : "memory");
}
__device__ __forceinline__ void bulk_g2s(unsigned dst, const void* src, unsigned bytes,
                                         unsigned mbar) {
    asm volatile("cp.async.bulk.shared::cluster.global.mbarrier::complete_tx::bytes "
                 "[%0], [%1], %2, [%3];"
                 :: "r"(dst), "l"(src), "r"(bytes), "r"(mbar) : "memory");
}
__device__ __forceinline__ void mbar_wait(unsigned mbar, unsigned parity) {
    unsigned done;
    asm volatile(
        "{\n\t.reg .pred p;\n\t"
        "mbarrier.try_wait.parity.acquire.cta.shared::cta.b64 p, [%1], %2;\n\t"
        "selp.b32 %0, 1, 0, p;\n\t}"
        : "=r"(done) : "r"(mbar), "r"(parity) : "memory");
    if (!done) {
        asm volatile(
            "{\n\t.reg .pred P1;\n\t"
            "WL_%=:\n\t"
            "mbarrier.try_wait.parity.acquire.cta.shared::cta.b64 P1, [%0], %1, 0x989680;\n\t"
            "@P1 bra.uni WD_%=;\n\t"
            "bra.uni WL_%=;\n\t"
            "WD_%=:\n\t}"
            :: "r"(mbar), "r"(parity) : "memory");
    }
}
__device__ __forceinline__ void fence_async_shared() {
    asm volatile("fence.proxy.async.shared::cta;" ::: "memory");
}

struct CoefH {
    ull Ec0, Es0, Ec1, Es1, nEs0, nEs1;
    ull Oc0, Os0, Oc1, Os1, nOs0, nOs1;
    float lfc, lfs;     // lfs pre-negated
};

#define LDH(d, S, H) do {                                                        \
    lds_u64x2<(S)*STAGE_B + (H)*1024          >(rbase, (d).Ec0, (d).Es0);        \
    lds_u64x2<(S)*STAGE_B + (H)*1024 + 512    >(rbase, (d).Ec1, (d).Es1);        \
    lds_u64x2<(S)*STAGE_B + NS_OFF + (H)*512  >(rbase, (d).nEs0, (d).nEs1);      \
    lds_u64x2<(S)*STAGE_B + LAYER_B + (H)*1024      >(rbase, (d).Oc0, (d).Os0);  \
    lds_u64x2<(S)*STAGE_B + LAYER_B + (H)*1024 + 512>(rbase, (d).Oc1, (d).Os1);  \
    lds_u64x2<(S)*STAGE_B + LAYER_B + NS_OFF + (H)*512>(rbase, (d).nOs0, (d).nOs1); \
    lds_f32x2<(S)*STAGE_B + LAYER_B + LEFT_OFF + (H)*256>(lbase, (d).lfc, (d).lfs); \
} while (0)

__device__ __forceinline__ void stage_lower(ull* L, CoefH& A, int lane) {
    rotp2(L[0], L[1], A.Ec0, A.Es0, A.nEs0);
    rotp2(L[2], L[3], A.Ec1, A.Es1, A.nEs1);
    float pl0  = lo_f(L[0]);
    float pl15 = hi_f(L[3]);
    float vnL = __shfl_down_sync(FULLM, pl0, 1);   // lane31 junk safe (identity gate)
    float lvL = __shfl_up_sync  (FULLM, pl15, 1);  // lane0 junk safe (identity left gate)
    float baseL = A.lfc * pl0;
    rotp2(L[1], L[2], A.Oc0, A.Os0, A.nOs0);
    ull Ql = pk(hi_f(L[0]), vnL);
    rotp2(L[3], Ql, A.Oc1, A.Os1, A.nOs1);
    float nv0 = fmaf(A.lfs, lvL, baseL);
    L[0] = pk(nv0, lo_f(Ql));
}

// Both-halves stage. Seam via index-mode wraparound shuffles (R13 scheme).
__device__ __forceinline__ void stage_both(ull* L, ull* U, CoefH& A, CoefH& Bc,
                                           int lane, int idxn, int idxp) {
    rotp2(L[0], L[1], A.Ec0, A.Es0, A.nEs0);
    rotp2(L[2], L[3], A.Ec1, A.Es1, A.nEs1);
    rotp2(U[0], U[1], Bc.Ec0, Bc.Es0, Bc.nEs0);
    rotp2(U[2], U[3], Bc.Ec1, Bc.Es1, Bc.nEs1);
    float pl0  = lo_f(L[0]);
    float pl15 = hi_f(L[3]);
    float pu0  = lo_f(U[0]);
    float pu15 = hi_f(U[3]);

    float y   = (lane == 0)  ? pu0  : pl0;
    float z   = (lane == 31) ? pl15 : pu15;
    float vnL = __shfl_sync(FULLM, y, idxn);       // lane31 <- v256
    float lvU = __shfl_sync(FULLM, z, idxp);       // lane0  <- v255
    float lvL = __shfl_up_sync  (FULLM, pl15, 1);  // lane0 junk safe
    float vnU = __shfl_down_sync(FULLM, pu0, 1);   // lane31 junk safe (511/512 identity)

    rotp2(L[1], L[2], A.Oc0, A.Os0, A.nOs0);
    ull Ql = pk(hi_f(L[0]), vnL);
    rotp2(L[3], Ql, A.Oc1, A.Os1, A.nOs1);
    float nv0 = fmaf(A.lfs, lvL, A.lfc * pl0);
    L[0] = pk(nv0, lo_f(Ql));

    rotp2(U[1], U[2], Bc.Oc0, Bc.Os0, Bc.nOs0);
    ull Qu = pk(hi_f(U[0]), vnU);
    rotp2(U[3], Qu, Bc.Oc1, Bc.Os1, Bc.nOs1);
    float nu0 = fmaf(Bc.lfs, lvU, Bc.lfc * pu0);
    U[0] = pk(nu0, lo_f(Qu));
}

__global__ void __launch_bounds__(64, 1) apply_kernel(
    const float* __restrict__ x,
    const float* __restrict__ bias,
    float* __restrict__ out)
{
    extern __shared__ __align__(128) char sbuf[];
    __shared__ __align__(8) unsigned long long mbar[3];

    const int tid  = threadIdx.x;
    const int lane = tid & 31;
    const int row  = blockIdx.x * 2 + (tid >> 5);
    const int idxn = (lane + 1) & 31;
    const int idxp = (lane - 1) & 31;

    if (tid == 0) {
        mbar_init(s2u(&mbar[0]), 1);
        mbar_init(s2u(&mbar[1]), 1);
        mbar_init(s2u(&mbar[2]), 1);
    }

    ull L[4], U[4];
    {
        const float4* xl = reinterpret_cast<const float4*>(x + (size_t)row * N_WIRES + 8 * lane);
        const float4* xu = reinterpret_cast<const float4*>(x + (size_t)row * N_WIRES + 256 + 8 * lane);
        float4 a0 = xl[0], a1 = xl[1], b0 = xu[0], b1 = xu[1];
        L[0] = pk(a0.x, a1.x); L[1] = pk(a0.y, a1.y);
        L[2] = pk(a0.z, a1.z); L[3] = pk(a0.w, a1.w);
        U[0] = pk(b0.x, b1.x); U[1] = pk(b0.y, b1.y);
        U[2] = pk(b0.z, b1.z); U[3] = pk(b0.w, b1.w);
    }

    __syncthreads();

    if (tid == 0) {
        #pragma unroll
        for (int pc = 0; pc < 3; ++pc) {
            unsigned mb = s2u(&mbar[pc]);
            mbar_expect_tx(mb, CHUNK_B);
            bulk_g2s(s2u(sbuf) + pc * CHUNK_B, g_tab + (size_t)pc * CHUNK_B, CHUNK_B, mb);
        }
    }

    const unsigned sb = s2u(sbuf);
    unsigned rbase = sb + lane * 16;
    unsigned lbase = sb + lane * 8;

    CoefH A0, A1, B0, B1;
    int rb = 0;
    #pragma unroll 1
    for (int c = 0; c < NCHUNK; ++c) {
        mbar_wait(s2u(&mbar[rb]), (unsigned)((c / 3) & 1));

        if (c >= MID_LO && c <= MID_HI) {
            LDH(A0, 0, 0);  LDH(B0, 0, 1);
            LDH(A1, 1, 0);  LDH(B1, 1, 1);   stage_both(L, U, A0, B0, lane, idxn, idxp);
            LDH(A0, 2, 0);  LDH(B0, 2, 1);   stage_both(L, U, A1, B1, lane, idxn, idxp);
            LDH(A1, 3, 0);  LDH(B1, 3, 1);   stage_both(L, U, A0, B0, lane, idxn, idxp);
            LDH(A0, 4, 0);  LDH(B0, 4, 1);   stage_both(L, U, A1, B1, lane, idxn, idxp);
            LDH(A1, 5, 0);  LDH(B1, 5, 1);   stage_both(L, U, A0, B0, lane, idxn, idxp);
            LDH(A0, 6, 0);  LDH(B0, 6, 1);   stage_both(L, U, A1, B1, lane, idxn, idxp);
            LDH(A1, 7, 0);  LDH(B1, 7, 1);   stage_both(L, U, A0, B0, lane, idxn, idxp);
            LDH(A0, 8, 0);  LDH(B0, 8, 1);   stage_both(L, U, A1, B1, lane, idxn, idxp);
            LDH(A1, 9, 0);  LDH(B1, 9, 1);   stage_both(L, U, A0, B0, lane, idxn, idxp);
            stage_both(L, U, A1, B1, lane, idxn, idxp);
        } else {
            LDH(A0, 0, 0);
            LDH(A1, 1, 0);   stage_lower(L, A0, lane);
            LDH(A0, 2, 0);   stage_lower(L, A1, lane);
            LDH(A1, 3, 0);   stage_lower(L, A0, lane);
            LDH(A0, 4, 0);   stage_lower(L, A1, lane);
            LDH(A1, 5, 0);   stage_lower(L, A0, lane);
            LDH(A0, 6, 0);   stage_lower(L, A1, lane);
            LDH(A1, 7, 0);   stage_lower(L, A0, lane);
            LDH(A0, 8, 0);   stage_lower(L, A1, lane);
            LDH(A1, 9, 0);   stage_lower(L, A0, lane);
            stage_lower(L, A1, lane);
        }

        __syncthreads();
        if (tid == 0 && c + 3 < NCHUNK) {
            fence_async_shared();
            unsigned mb = s2u(&mbar[rb]);
            mbar_expect_tx(mb, CHUNK_B);
            bulk_g2s(sb + rb * CHUNK_B, g_tab + (size_t)(c + 3) * CHUNK_B, CHUNK_B, mb);
        }

        rb = (rb == 2) ? 0 : rb + 1;
        rbase += CHUNK_B;
        lbase += CHUNK_B;
        if (rb == 0) { rbase -= 3 * CHUNK_B; lbase -= 3 * CHUNK_B; }
    }

    {
        const float* bl = bias + 8 * lane;
        float* ol = out + (size_t)row * N_WIRES + 8 * lane;
        float4 bb0 = *reinterpret_cast<const float4*>(bl);
        float4 bb1 = *reinterpret_cast<const float4*>(bl + 4);
        float4 bb2 = *reinterpret_cast<const float4*>(bl + 256);
        float4 bb3 = *reinterpret_cast<const float4*>(bl + 260);
        float4 o0, o1, o2, o3;
        o0.x = lo_f(L[0]) + bb0.x; o0.y = lo_f(L[1]) + bb0.y;
        o0.z = lo_f(L[2]) + bb0.z; o0.w = lo_f(L[3]) + bb0.w;
        o1.x = hi_f(L[0]) + bb1.x; o1.y = hi_f(L[1]) + bb1.y;
        o1.z = hi_f(L[2]) + bb1.z; o1.w = hi_f(L[3]) + bb1.w;
        o2.x = lo_f(U[0]) + bb2.x; o2.y = lo_f(U[1]) + bb2.y;
        o2.z = lo_f(U[2]) + bb2.z; o2.w = lo_f(U[3]) + bb2.w;
        o3.x = hi_f(U[0]) + bb3.x; o3.y = hi_f(U[1]) + bb3.y;
        o3.z = hi_f(U[2]) + bb3.z; o3.w = hi_f(U[3]) + bb3.w;
        *reinterpret_cast<float4*>(ol)       = o0;
        *reinterpret_cast<float4*>(ol + 4)   = o1;
        *reinterpret_cast<float4*>(ol + 256) = o2;
        *reinterpret_cast<float4*>(ol + 260) = o3;
    }
}

extern "C" void kernel_launch(void* const* d_in, const int* in_sizes, int n_in,
                              void* d_out, int out_size) {
    const float* x      = (const float*)d_in[0];
    const float* thetas = (const float*)d_in[1];
    const float* bias   = (const float*)d_in[2];
    float* out = (float*)d_out;

    build_cs_kernel<<<(T_PAD + 3) / 4, 512>>>(thetas);

    cudaFuncSetAttribute(apply_kernel,
                         cudaFuncAttributeMaxDynamicSharedMemorySize, 3 * CHUNK_B);

    int B = in_sizes[0] / N_WIRES;   // 256
    apply_kernel<<<B / 2, 64, 3 * CHUNK_B>>>(x, bias, out);
}

// round 15
// speedup vs baseline: 1.0528x; 1.0528x over previous
#include <cuda_runtime.h>

// Pyramid Givens circuit, n = m = 512, B = 256.
// Layer t in [0,1021): gates (i,i+1) for i ≡ t (mod 2), 0 <= i <= min(t, 1020-t).
// theta index: q=(t+i)/2, tidx = q(q+1)/2 + q - i.  Gate: a'=c*a+s*b ; b'=c*b-s*a.
//
// Lane L owns wires [8L,8L+7] (h=0) and [256+8L,256+8L+7] (h=1), packed as
// (v_{w+k}, v_{w+k+4}). Upper half active only for t in [255,765]; chunks
// (36 layers) phase-split into both-halves / lower-only straight-line bodies.
// Left-gate coefs packed per-lane for both halves (one 16B load, packed math).
// 2-buffer cp.async.bulk pipeline. All smem loads: 32-bit base + immediate.

#define N_WIRES   512
#define CHUNK_L   36
#define NCHUNK    29                   // 29*36 = 1044 layers (tail identity)
#define T_PAD     (NCHUNK * CHUNK_L)   // 1044
#define LAYER_B   2560                 // rot 2048 + left 512
#define LEFT_OFF  2048
#define CHUNK_B   (CHUNK_L * LAYER_B)  // 92160
#define STAGE_B   (2 * LAYER_B)        // 5120
#define MID_LO    7                    // chunks 7..21 cover t in [252,791] ⊇ [255,765]
#define MID_HI    21

typedef unsigned long long ull;

// Per layer t (stride LAYER_B):
//   [0,2048):      rot double2 {c2,s2}, entry at h*1024 + r*512 + lane*16
//   [2048,2560):   left-gate 16B per lane: {lfc_L, lfc_U} @+0, {lfs_L, lfs_U} @+8
//                  (sines pre-negated). Gate (w-1, w) per half.
// Inactive gates stored as identity.
__device__ __align__(128) char g_tab[(size_t)T_PAD * LAYER_B];   // ~2.67 MB

__device__ __forceinline__ float2 cs_of(const float* __restrict__ th, int t, int i) {
    if (t <= 1020 && i >= 0 && i <= t && i <= 1020 - t && (((i ^ t) & 1) == 0)) {
        int q = (t + i) >> 1;
        int tidx = (q * (q + 1)) / 2 + q - i;
        float s, c;
        __sincosf(th[tidx], &s, &c);    // |theta| <= pi
        return make_float2(c, s);
    }
    return make_float2(1.0f, 0.0f);
}

// 512 threads = 4 layers per block.
__global__ void build_cs_kernel(const float* __restrict__ thetas) {
    int t    = blockIdx.x * 4 + (threadIdx.x >> 7);
    if (t >= T_PAD) return;
    int h    = (threadIdx.x >> 6) & 1;
    int r    = (threadIdx.x >> 5) & 1;
    int lane = threadIdx.x & 31;
    int w    = 256 * h + 8 * lane;
    int ilo, ihi;
    if ((t & 1) == 0) { ilo = w + 2 * r;     ihi = ilo + 4; }
    else              { ilo = w + 2 * r + 1; ihi = ilo + 4; }
    float2 a = cs_of(thetas, t, ilo);
    float2 b = cs_of(thetas, t, ihi);
    char* base = g_tab + (size_t)t * LAYER_B;
    float2* dst = reinterpret_cast<float2*>(base + h * 1024 + r * 512 + lane * 16);
    dst[0] = make_float2(a.x, b.x);   // c2
    dst[1] = make_float2(a.y, b.y);   // s2
    if (r == 0) {
        float2 lf = cs_of(thetas, t, w - 1);
        char* lp = base + LEFT_OFF + lane * 16;
        *reinterpret_cast<float*>(lp + h * 4)     = lf.x;    // lfc (lo:h0, hi:h1)
        *reinterpret_cast<float*>(lp + 8 + h * 4) = -lf.y;   // lfs pre-negated
    }
}

// ---- f32x2 helpers ----
__device__ __forceinline__ ull mul2(ull a, ull b) {
    ull d; asm("mul.rn.f32x2 %0, %1, %2;" : "=l"(d) : "l"(a), "l"(b)); return d;
}
__device__ __forceinline__ ull fma2(ull a, ull b, ull c) {
    ull d; asm("fma.rn.f32x2 %0, %1, %2, %3;" : "=l"(d) : "l"(a), "l"(b), "l"(c)); return d;
}
__device__ __forceinline__ float lo_f(ull p) {
    float lo; asm("{ .reg .b32 hi_; mov.b64 {%0, hi_}, %1; }" : "=f"(lo) : "l"(p)); return lo;
}
__device__ __forceinline__ float hi_f(ull p) {
    float hi; asm("{ .reg .b32 lo_; mov.b64 {lo_, %0}, %1; }" : "=f"(hi) : "l"(p)); return hi;
}
__device__ __forceinline__ ull pk(float lo, float hi) {
    ull d; asm("mov.b64 %0, {%1, %2};" : "=l"(d) : "f"(lo), "f"(hi)); return d;
}

#define SGNMASK 0x8000000080000000ULL
#define FULLM   0xffffffffu

__device__ __forceinline__ void rotp2(ull& a, ull& b, ull c2, ull s2, ull ns2) {
    ull t1 = mul2(s2, b);
    ull na = fma2(c2, a, t1);
    ull t2 = mul2(ns2, a);
    b = fma2(c2, b, t2);
    a = na;
}

// ---- 32-bit shared loads with immediate offsets ----
template<int OFF>
__device__ __forceinline__ void lds_u64x2(unsigned base, ull& x, ull& y) {
    asm volatile("ld.shared.v2.u64 {%0, %1}, [%2+%3];"
                 : "=l"(x), "=l"(y) : "r"(base), "n"(OFF));
}

// ---- bulk-copy / mbarrier helpers ----
__device__ __forceinline__ unsigned s2u(const void* p) {
    return (unsigned)__cvta_generic_to_shared(p);
}
__device__ __forceinline__ void mbar_init(unsigned mbar, unsigned cnt) {
    asm volatile("mbarrier.init.shared.b64 [%0], %1;" :: "r"(mbar), "r"(cnt) : "memory");
}
__device__ __forceinline__ void mbar_expect_tx(unsigned mbar, unsigned bytes) {
    asm volatile("mbarrier.arrive.expect_tx.shared.b64 _, [%0], %1;"
                 :: "r"(mbar), "r"(bytes) : "memory");
}
__device__ __forceinline__ void bulk_g2s(unsigned dst, const void* src, unsigned bytes,
                                         unsigned mbar) {
    asm volatile("cp.async.bulk.shared::cluster.global.mbarrier::complete_tx::bytes "
                 "[%0], [%1], %2, [%3];"
                 :: "r"(dst), "l"(src), "r"(bytes), "r"(mbar) : "memory");
}
__device__ __forceinline__ void mbar_wait(unsigned mbar, unsigned parity) {
    unsigned done;
    asm volatile(
        "{\n\t.reg .pred p;\n\t"
        "mbarrier.try_wait.parity.acquire.cta.shared::cta.b64 p, [%1], %2;\n\t"
        "selp.b32 %0, 1, 0, p;\n\t}"
        : "=r"(done) : "r"(mbar), "r"(parity) : "memory");
    if (!done) {
        asm volatile(
            "{\n\t.reg .pred P1;\n\t"
            "WL_%=:\n\t"
            "mbarrier.try_wait.parity.acquire.cta.shared::cta.b64 P1, [%0], %1, 0x989680;\n\t"
            "@P1 bra.uni WD_%=;\n\t"
            "bra.uni WL_%=;\n\t"
            "WD_%=:\n\t}"
            :: "r"(mbar), "r"(parity) : "memory");
    }
}
__device__ __forceinline__ void fence_async_shared() {
    asm volatile("fence.proxy.async.shared::cta;" ::: "memory");
}

struct CoefH {
    ull Ec0, Es0, Ec1, Es1;
    ull Oc0, Os0, Oc1, Os1;
    ull lfc2, lfs2;     // packed {L,U} left-gate; sines pre-negated
};

// Rot coefs for (stage S, half H).
#define LDROT(d, S, H) do {                                                      \
    lds_u64x2<(S)*STAGE_B + (H)*1024          >(rbase, (d).Ec0, (d).Es0);        \
    lds_u64x2<(S)*STAGE_B + (H)*1024 + 512    >(rbase, (d).Ec1, (d).Es1);        \
    lds_u64x2<(S)*STAGE_B + LAYER_B + (H)*1024      >(rbase, (d).Oc0, (d).Os0);  \
    lds_u64x2<(S)*STAGE_B + LAYER_B + (H)*1024 + 512>(rbase, (d).Oc1, (d).Os1);  \
} while (0)
#define LDLEFT(d, S) \
    lds_u64x2<(S)*STAGE_B + LAYER_B + LEFT_OFF>(lbase, (d).lfc2, (d).lfs2)

#define LDB(dA, dB, S) do { LDROT(dA, S, 0); LDROT(dB, S, 1); LDLEFT(dA, S); } while (0)
#define LDL(dA, S)     do { LDROT(dA, S, 0); LDLEFT(dA, S); } while (0)

__device__ __forceinline__ void stage_lower(ull* L, CoefH& A, int lane) {
    ull nAs0 = A.Es0 ^ SGNMASK, nAs1 = A.Es1 ^ SGNMASK;
    ull nAo0 = A.Os0 ^ SGNMASK, nAo1 = A.Os1 ^ SGNMASK;
    rotp2(L[0], L[1], A.Ec0, A.Es0, nAs0);
    rotp2(L[2], L[3], A.Ec1, A.Es1, nAs1);
    float pl0  = lo_f(L[0]);
    float pl15 = hi_f(L[3]);
    float vnL = __shfl_down_sync(FULLM, pl0, 1);   // lane31 junk safe (identity gate)
    float lvL = __shfl_up_sync  (FULLM, pl15, 1);  // lane0 junk safe (identity left gate)
    float baseL = lo_f(A.lfc2) * pl0;
    rotp2(L[1], L[2], A.Oc0, A.Os0, nAo0);
    ull Ql = pk(hi_f(L[0]), vnL);
    rotp2(L[3], Ql, A.Oc1, A.Os1, nAo1);
    float nv0 = fmaf(lo_f(A.lfs2), lvL, baseL);
    L[0] = pk(nv0, lo_f(Ql));
}

// Both-halves stage; seam via index-mode wraparound shuffles; packed v0 update.
__device__ __forceinline__ void stage_both(ull* L, ull* U, CoefH& A, CoefH& Bc,
                                           int lane, int idxn, int idxp) {
    ull nAs0 = A.Es0 ^ SGNMASK, nAs1 = A.Es1 ^ SGNMASK;
    ull nAo0 = A.Os0 ^ SGNMASK, nAo1 = A.Os1 ^ SGNMASK;
    ull nBs0 = Bc.Es0 ^ SGNMASK, nBs1 = Bc.Es1 ^ SGNMASK;
    ull nBo0 = Bc.Os0 ^ SGNMASK, nBo1 = Bc.Os1 ^ SGNMASK;

    rotp2(L[0], L[1], A.Ec0, A.Es0, nAs0);
    rotp2(L[2], L[3], A.Ec1, A.Es1, nAs1);
    rotp2(U[0], U[1], Bc.Ec0, Bc.Es0, nBs0);
    rotp2(U[2], U[3], Bc.Ec1, Bc.Es1, nBs1);
    float pl0  = lo_f(L[0]);
    float pl15 = hi_f(L[3]);
    float pu0  = lo_f(U[0]);
    float pu15 = hi_f(U[3]);

    float y   = (lane == 0)  ? pu0  : pl0;
    float z   = (lane == 31) ? pl15 : pu15;
    float vnL = __shfl_sync(FULLM, y, idxn);       // lane31 <- v256
    float lvU = __shfl_sync(FULLM, z, idxp);       // lane0  <- v255
    float lvL = __shfl_up_sync  (FULLM, pl15, 1);  // lane0 junk safe
    float vnU = __shfl_down_sync(FULLM, pu0, 1);   // lane31 junk safe (511/512 identity)

    rotp2(L[1], L[2], A.Oc0, A.Os0, nAo0);
    ull Ql = pk(hi_f(L[0]), vnL);
    rotp2(L[3], Ql, A.Oc1, A.Os1, nAo1);

    rotp2(U[1], U[2], Bc.Oc0, Bc.Os0, nBo0);
    ull Qu = pk(hi_f(U[0]), vnU);
    rotp2(U[3], Qu, Bc.Oc1, Bc.Os1, nBo1);

    // packed left-gate: (nv0, nu0) = lfc2*(pl0,pu0) + lfs2*(lvL,lvU)
    ull p02 = pk(pl0, pu0);
    ull lv2 = pk(lvL, lvU);
    ull nv2 = fma2(A.lfc2, p02, mul2(A.lfs2, lv2));
    L[0] = pk(lo_f(nv2), lo_f(Ql));
    U[0] = pk(hi_f(nv2), lo_f(Qu));
}

__global__ void __launch_bounds__(64, 1) apply_kernel(
    const float* __restrict__ x,
    const float* __restrict__ bias,
    float* __restrict__ out)
{
    extern __shared__ __align__(128) char sbuf[];       // 2 * CHUNK_B dynamic
    __shared__ __align__(8) unsigned long long mbar[2];

    const int tid  = threadIdx.x;
    const int lane = tid & 31;
    const int row  = blockIdx.x * 2 + (tid >> 5);
    const int idxn = (lane + 1) & 31;
    const int idxp = (lane - 1) & 31;

    if (tid == 0) {
        mbar_init(s2u(&mbar[0]), 1);
        mbar_init(s2u(&mbar[1]), 1);
    }

    ull L[4], U[4];
    {
        const float4* xl = reinterpret_cast<const float4*>(x + (size_t)row * N_WIRES + 8 * lane);
        const float4* xu = reinterpret_cast<const float4*>(x + (size_t)row * N_WIRES + 256 + 8 * lane);
        float4 a0 = xl[0], a1 = xl[1], b0 = xu[0], b1 = xu[1];
        L[0] = pk(a0.x, a1.x); L[1] = pk(a0.y, a1.y);
        L[2] = pk(a0.z, a1.z); L[3] = pk(a0.w, a1.w);
        U[0] = pk(b0.x, b1.x); U[1] = pk(b0.y, b1.y);
        U[2] = pk(b0.z, b1.z); U[3] = pk(b0.w, b1.w);
    }

    __syncthreads();

    if (tid == 0) {
        #pragma unroll
        for (int pc = 0; pc < 2; ++pc) {
            unsigned mb = s2u(&mbar[pc]);
            mbar_expect_tx(mb, CHUNK_B);
            bulk_g2s(s2u(sbuf) + pc * CHUNK_B, g_tab + (size_t)pc * CHUNK_B, CHUNK_B, mb);
        }
    }

    const unsigned sb = s2u(sbuf);

    CoefH A0, A1, B0, B1;
    #pragma unroll 1
    for (int c = 0; c < NCHUNK; ++c) {
        const int bufo = (c & 1) ? CHUNK_B : 0;
        mbar_wait(s2u(&mbar[c & 1]), (unsigned)((c >> 1) & 1));
        const unsigned rbase = sb + bufo + lane * 16;
        const unsigned lbase = rbase;   // left entries also lane*16

        if (c >= MID_LO && c <= MID_HI) {
            LDB(A0, B0, 0);
            LDB(A1, B1, 1);   stage_both(L, U, A0, B0, lane, idxn, idxp);
            LDB(A0, B0, 2);   stage_both(L, U, A1, B1, lane, idxn, idxp);
            LDB(A1, B1, 3);   stage_both(L, U, A0, B0, lane, idxn, idxp);
            LDB(A0, B0, 4);   stage_both(L, U, A1, B1, lane, idxn, idxp);
            LDB(A1, B1, 5);   stage_both(L, U, A0, B0, lane, idxn, idxp);
            LDB(A0, B0, 6);   stage_both(L, U, A1, B1, lane, idxn, idxp);
            LDB(A1, B1, 7);   stage_both(L, U, A0, B0, lane, idxn, idxp);
            LDB(A0, B0, 8);   stage_both(L, U, A1, B1, lane, idxn, idxp);
            LDB(A1, B1, 9);   stage_both(L, U, A0, B0, lane, idxn, idxp);
            LDB(A0, B0, 10);  stage_both(L, U, A1, B1, lane, idxn, idxp);
            LDB(A1, B1, 11);  stage_both(L, U, A0, B0, lane, idxn, idxp);
            LDB(A0, B0, 12);  stage_both(L, U, A1, B1, lane, idxn, idxp);
            LDB(A1, B1, 13);  stage_both(L, U, A0, B0, lane, idxn, idxp);
            LDB(A0, B0, 14);  stage_both(L, U, A1, B1, lane, idxn, idxp);
            LDB(A1, B1, 15);  stage_both(L, U, A0, B0, lane, idxn, idxp);
            LDB(A0, B0, 16);  stage_both(L, U, A1, B1, lane, idxn, idxp);
            LDB(A1, B1, 17);  stage_both(L, U, A0, B0, lane, idxn, idxp);
            stage_both(L, U, A1, B1, lane, idxn, idxp);
        } else {
            LDL(A0, 0);
            LDL(A1, 1);    stage_lower(L, A0, lane);
            LDL(A0, 2);    stage_lower(L, A1, lane);
            LDL(A1, 3);    stage_lower(L, A0, lane);
            LDL(A0, 4);    stage_lower(L, A1, lane);
            LDL(A1, 5);    stage_lower(L, A0, lane);
            LDL(A0, 6);    stage_lower(L, A1, lane);
            LDL(A1, 7);    stage_lower(L, A0, lane);
            LDL(A0, 8);    stage_lower(L, A1, lane);
            LDL(A1, 9);    stage_lower(L, A0, lane);
            LDL(A0, 10);   stage_lower(L, A1, lane);
            LDL(A1, 11);   stage_lower(L, A0, lane);
            LDL(A0, 12);   stage_lower(L, A1, lane);
            LDL(A1, 13);   stage_lower(L, A0, lane);
            LDL(A0, 14);   stage_lower(L, A1, lane);
            LDL(A1, 15);   stage_lower(L, A0, lane);
            LDL(A0, 16);   stage_lower(L, A1, lane);
            LDL(A1, 17);   stage_lower(L, A0, lane);
            stage_lower(L, A1, lane);
        }

        __syncthreads();   // both warps done reading this buffer
        if (tid == 0 && c + 2 < NCHUNK) {
            fence_async_shared();
            unsigned mb = s2u(&mbar[c & 1]);
            mbar_expect_tx(mb, CHUNK_B);
            bulk_g2s(sb + bufo, g_tab + (size_t)(c + 2) * CHUNK_B, CHUNK_B, mb);
        }
    }

    {
        const float* bl = bias + 8 * lane;
        float* ol = out + (size_t)row * N_WIRES + 8 * lane;
        float4 bb0 = *reinterpret_cast<const float4*>(bl);
        float4 bb1 = *reinterpret_cast<const float4*>(bl + 4);
        float4 bb2 = *reinterpret_cast<const float4*>(bl + 256);
        float4 bb3 = *reinterpret_cast<const float4*>(bl + 260);
        float4 o0, o1, o2, o3;
        o0.x = lo_f(L[0]) + bb0.x; o0.y = lo_f(L[1]) + bb0.y;
        o0.z = lo_f(L[2]) + bb0.z; o0.w = lo_f(L[3]) + bb0.w;
        o1.x = hi_f(L[0]) + bb1.x; o1.y = hi_f(L[1]) + bb1.y;
        o1.z = hi_f(L[2]) + bb1.z; o1.w = hi_f(L[3]) + bb1.w;
        o2.x = lo_f(U[0]) + bb2.x; o2.y = lo_f(U[1]) + bb2.y;
        o2.z = lo_f(U[2]) + bb2.z; o2.w = lo_f(U[3]) + bb2.w;
        o3.x = hi_f(U[0]) + bb3.x; o3.y = hi_f(U[1]) + bb3.y;
        o3.z = hi_f(U[2]) + bb3.z; o3.w = hi_f(U[3]) + bb3.w;
        *reinterpret_cast<float4*>(ol)       = o0;
        *reinterpret_cast<float4*>(ol + 4)   = o1;
        *reinterpret_cast<float4*>(ol + 256) = o2;
        *reinterpret_cast<float4*>(ol + 260) = o3;
    }
}

extern "C" void kernel_launch(void* const* d_in, const int* in_sizes, int n_in,
                              void* d_out, int out_size) {
    const float* x      = (const float*)d_in[0];
    const float* thetas = (const float*)d_in[1];
    const float* bias   = (const float*)d_in[2];
    float* out = (float*)d_out;

    build_cs_kernel<<<(T_PAD + 3) / 4, 512>>>(thetas);

    cudaFuncSetAttribute(apply_kernel,
                         cudaFuncAttributeMaxDynamicSharedMemorySize, 2 * CHUNK_B);

    int B = in_sizes[0] / N_WIRES;   // 256
    apply_kernel<<<B / 2, 64, 2 * CHUNK_B>>>(x, bias, out);
}

// round 16
// speedup vs baseline: 1.1077x; 1.0521x over previous
#include <cuda_runtime.h>

// Pyramid Givens circuit, n = m = 512, B = 256.
// Layer t in [0,1021): gates (i,i+1) for i ≡ t (mod 2), 0 <= i <= min(t, 1020-t).
// theta index: q=(t+i)/2, tidx = q(q+1)/2 + q - i.  Gate: a'=c*a+s*b ; b'=c*b-s*a.
//
// Lane L owns wires [8L,8L+7] (h=0) and [256+8L,256+8L+7] (h=1), packed as
// (v_{w+k}, v_{w+k+4}). Upper half active only for t in [255,765]; chunks
// (28 layers) phase-split into both-halves / lower-only straight-line bodies.
// Rotation uses sub.rn.f32x2 (no sign-flip XORs). Left-gate coefs packed
// per-lane for both halves. 3-buffer cp.async.bulk pipeline; all smem loads
// 32-bit base + compile-time immediate.

#define N_WIRES   512
#define CHUNK_L   28
#define NCHUNK    37                   // 37*28 = 1036 layers (tail identity)
#define T_PAD     (NCHUNK * CHUNK_L)   // 1036
#define LAYER_B   2560                 // rot 2048 + left 512
#define LEFT_OFF  2048
#define CHUNK_B   (CHUNK_L * LAYER_B)  // 71680
#define STAGE_B   (2 * LAYER_B)        // 5120
#define MID_LO    9                    // chunks 9..27 cover t in [252,783] ⊇ [255,765]
#define MID_HI    27

typedef unsigned long long ull;

// Per layer t (stride LAYER_B):
//   [0,2048):    rot double2 {c2,s2}, entry at h*1024 + r*512 + lane*16
//   [2048,2560): left-gate 16B per lane: {lfc_L,lfc_U} @+0, {lfs_L,lfs_U} @+8
//                (sines pre-negated). Gate (w-1, w) per half.
// Inactive gates stored as identity.
__device__ __align__(128) char g_tab[(size_t)T_PAD * LAYER_B];   // ~2.65 MB

__device__ __forceinline__ float2 cs_of(const float* __restrict__ th, int t, int i) {
    if (t <= 1020 && i >= 0 && i <= t && i <= 1020 - t && (((i ^ t) & 1) == 0)) {
        int q = (t + i) >> 1;
        int tidx = (q * (q + 1)) / 2 + q - i;
        float s, c;
        __sincosf(th[tidx], &s, &c);    // |theta| <= pi
        return make_float2(c, s);
    }
    return make_float2(1.0f, 0.0f);
}

// 512 threads = 4 layers per block.
__global__ void build_cs_kernel(const float* __restrict__ thetas) {
    int t    = blockIdx.x * 4 + (threadIdx.x >> 7);
    if (t >= T_PAD) return;
    int h    = (threadIdx.x >> 6) & 1;
    int r    = (threadIdx.x >> 5) & 1;
    int lane = threadIdx.x & 31;
    int w    = 256 * h + 8 * lane;
    int ilo, ihi;
    if ((t & 1) == 0) { ilo = w + 2 * r;     ihi = ilo + 4; }
    else              { ilo = w + 2 * r + 1; ihi = ilo + 4; }
    float2 a = cs_of(thetas, t, ilo);
    float2 b = cs_of(thetas, t, ihi);
    char* base = g_tab + (size_t)t * LAYER_B;
    float2* dst = reinterpret_cast<float2*>(base + h * 1024 + r * 512 + lane * 16);
    dst[0] = make_float2(a.x, b.x);   // c2
    dst[1] = make_float2(a.y, b.y);   // s2
    if (r == 0) {
        float2 lf = cs_of(thetas, t, w - 1);
        char* lp = base + LEFT_OFF + lane * 16;
        *reinterpret_cast<float*>(lp + h * 4)     = lf.x;    // lfc (lo:h0, hi:h1)
        *reinterpret_cast<float*>(lp + 8 + h * 4) = -lf.y;   // lfs pre-negated
    }
}

// ---- f32x2 helpers ----
__device__ __forceinline__ ull mul2(ull a, ull b) {
    ull d; asm("mul.rn.f32x2 %0, %1, %2;" : "=l"(d) : "l"(a), "l"(b)); return d;
}
__device__ __forceinline__ ull fma2(ull a, ull b, ull c) {
    ull d; asm("fma.rn.f32x2 %0, %1, %2, %3;" : "=l"(d) : "l"(a), "l"(b), "l"(c)); return d;
}
__device__ __forceinline__ ull sub2(ull a, ull b) {
    ull d; asm("sub.rn.f32x2 %0, %1, %2;" : "=l"(d) : "l"(a), "l"(b)); return d;
}
__device__ __forceinline__ float lo_f(ull p) {
    float lo; asm("{ .reg .b32 hi_; mov.b64 {%0, hi_}, %1; }" : "=f"(lo) : "l"(p)); return lo;
}
__device__ __forceinline__ float hi_f(ull p) {
    float hi; asm("{ .reg .b32 lo_; mov.b64 {lo_, %0}, %1; }" : "=f"(hi) : "l"(p)); return hi;
}
__device__ __forceinline__ ull pk(float lo, float hi) {
    ull d; asm("mov.b64 %0, {%1, %2};" : "=l"(d) : "f"(lo), "f"(hi)); return d;
}

#define FULLM 0xffffffffu

// Packed Givens, no negation needed:
//   a' = c*a + s*b ; b' = c*b - s*a
__device__ __forceinline__ void rotp(ull& a, ull& b, ull c2, ull s2) {
    ull t1 = mul2(s2, b);
    ull na = fma2(c2, a, t1);
    ull t2 = mul2(s2, a);
    ull t3 = mul2(c2, b);
    b = sub2(t3, t2);
    a = na;
}

// ---- 32-bit shared loads with immediate offsets ----
template<int OFF>
__device__ __forceinline__ void lds_u64x2(unsigned base, ull& x, ull& y) {
    asm volatile("ld.shared.v2.u64 {%0, %1}, [%2+%3];"
                 : "=l"(x), "=l"(y) : "r"(base), "n"(OFF));
}

// ---- bulk-copy / mbarrier helpers ----
__device__ __forceinline__ unsigned s2u(const void* p) {
    return (unsigned)__cvta_generic_to_shared(p);
}
__device__ __forceinline__ void mbar_init(unsigned mbar, unsigned cnt) {
    asm volatile("mbarrier.init.shared.b64 [%0], %1;" :: "r"(mbar), "r"(cnt) : "memory");
}
__device__ __forceinline__ void mbar_expect_tx(unsigned mbar, unsigned bytes) {
    asm volatile("mbarrier.arrive.expect_tx.shared.b64 _, [%0], %1;"
                 :: "r"(mbar), "r"(bytes) : "memory");
}
__device__ __forceinline__ void bulk_g2s(unsigned dst, const void* src, unsigned bytes,
                                         unsigned mbar) {
    asm volatile("cp.async.bulk.shared::cluster.global.mbarrier::complete_tx::bytes "
                 "[%0], [%1], %2, [%3];"
                 :: "r"(dst), "l"(src), "r"(bytes), "r"(mbar) : "memory");
}
__device__ __forceinline__ void mbar_wait(unsigned mbar, unsigned parity) {
    unsigned done;
    asm volatile(
        "{\n\t.reg .pred p;\n\t"
        "mbarrier.try_wait.parity.acquire.cta.shared::cta.b64 p, [%1], %2;\n\t"
        "selp.b32 %0, 1, 0, p;\n\t}"
        : "=r"(done) : "r"(mbar), "r"(parity) : "memory");
    if (!done) {
        asm volatile(
            "{\n\t.reg .pred P1;\n\t"
            "WL_%=:\n\t"
            "mbarrier.try_wait.parity.acquire.cta.shared::cta.b64 P1, [%0], %1, 0x989680;\n\t"
            "@P1 bra.uni WD_%=;\n\t"
            "bra.uni WL_%=;\n\t"
            "WD_%=:\n\t}"
            :: "r"(mbar), "r"(parity) : "memory");
    }
}
__device__ __forceinline__ void fence_async_shared() {
    asm volatile("fence.proxy.async.shared::cta;" ::: "memory");
}

struct CoefH {
    ull Ec0, Es0, Ec1, Es1;
    ull Oc0, Os0, Oc1, Os1;
    ull lfc2, lfs2;     // packed {L,U} left-gate; sines pre-negated
};

#define LDROT(d, S, H) do {                                                      \
    lds_u64x2<(S)*STAGE_B + (H)*1024          >(rbase, (d).Ec0, (d).Es0);        \
    lds_u64x2<(S)*STAGE_B + (H)*1024 + 512    >(rbase, (d).Ec1, (d).Es1);        \
    lds_u64x2<(S)*STAGE_B + LAYER_B + (H)*1024      >(rbase, (d).Oc0, (d).Os0);  \
    lds_u64x2<(S)*STAGE_B + LAYER_B + (H)*1024 + 512>(rbase, (d).Oc1, (d).Os1);  \
} while (0)
#define LDLEFT(d, S) \
    lds_u64x2<(S)*STAGE_B + LAYER_B + LEFT_OFF>(rbase, (d).lfc2, (d).lfs2)

#define LDB(dA, dB, S) do { LDROT(dA, S, 0); LDROT(dB, S, 1); LDLEFT(dA, S); } while (0)
#define LDL(dA, S)     do { LDROT(dA, S, 0); LDLEFT(dA, S); } while (0)

__device__ __forceinline__ void stage_lower(ull* L, CoefH& A, int lane) {
    rotp(L[0], L[1], A.Ec0, A.Es0);
    rotp(L[2], L[3], A.Ec1, A.Es1);
    float pl0  = lo_f(L[0]);
    float pl15 = hi_f(L[3]);
    float vnL = __shfl_down_sync(FULLM, pl0, 1);   // lane31 junk safe (identity gate)
    float lvL = __shfl_up_sync  (FULLM, pl15, 1);  // lane0 junk safe (identity left gate)
    float baseL = lo_f(A.lfc2) * pl0;
    rotp(L[1], L[2], A.Oc0, A.Os0);
    ull Ql = pk(hi_f(L[0]), vnL);
    rotp(L[3], Ql, A.Oc1, A.Os1);
    float nv0 = fmaf(lo_f(A.lfs2), lvL, baseL);    // lfs pre-negated
    L[0] = pk(nv0, lo_f(Ql));
}

// Both-halves stage; seam via index-mode wraparound shuffles; packed v0 update.
__device__ __forceinline__ void stage_both(ull* L, ull* U, CoefH& A, CoefH& Bc,
                                           int lane, int idxn, int idxp) {
    rotp(L[0], L[1], A.Ec0, A.Es0);
    rotp(L[2], L[3], A.Ec1, A.Es1);
    rotp(U[0], U[1], Bc.Ec0, Bc.Es0);
    rotp(U[2], U[3], Bc.Ec1, Bc.Es1);
    float pl0  = lo_f(L[0]);
    float pl15 = hi_f(L[3]);
    float pu0  = lo_f(U[0]);
    float pu15 = hi_f(U[3]);

    float y   = (lane == 0)  ? pu0  : pl0;
    float z   = (lane == 31) ? pl15 : pu15;
    float vnL = __shfl_sync(FULLM, y, idxn);       // lane31 <- v256
    float lvU = __shfl_sync(FULLM, z, idxp);       // lane0  <- v255
    float lvL = __shfl_up_sync  (FULLM, pl15, 1);  // lane0 junk safe
    float vnU = __shfl_down_sync(FULLM, pu0, 1);   // lane31 junk safe (511/512 identity)

    rotp(L[1], L[2], A.Oc0, A.Os0);
    ull Ql = pk(hi_f(L[0]), vnL);
    rotp(L[3], Ql, A.Oc1, A.Os1);

    rotp(U[1], U[2], Bc.Oc0, Bc.Os0);
    ull Qu = pk(hi_f(U[0]), vnU);
    rotp(U[3], Qu, Bc.Oc1, Bc.Os1);

    // packed left-gate: (nv0, nu0) = lfc2*(pl0,pu0) + lfs2*(lvL,lvU)
    ull p02 = pk(pl0, pu0);
    ull lv2 = pk(lvL, lvU);
    ull nv2 = fma2(A.lfc2, p02, mul2(A.lfs2, lv2));
    L[0] = pk(lo_f(nv2), lo_f(Ql));
    U[0] = pk(hi_f(nv2), lo_f(Qu));
}

__global__ void __launch_bounds__(64, 1) apply_kernel(
    const float* __restrict__ x,
    const float* __restrict__ bias,
    float* __restrict__ out)
{
    extern __shared__ __align__(128) char sbuf[];       // 3 * CHUNK_B dynamic
    __shared__ __align__(8) unsigned long long mbar[3];

    const int tid  = threadIdx.x;
    const int lane = tid & 31;
    const int row  = blockIdx.x * 2 + (tid >> 5);
    const int idxn = (lane + 1) & 31;
    const int idxp = (lane - 1) & 31;

    if (tid == 0) {
        mbar_init(s2u(&mbar[0]), 1);
        mbar_init(s2u(&mbar[1]), 1);
        mbar_init(s2u(&mbar[2]), 1);
    }

    ull L[4], U[4];
    {
        const float4* xl = reinterpret_cast<const float4*>(x + (size_t)row * N_WIRES + 8 * lane);
        const float4* xu = reinterpret_cast<const float4*>(x + (size_t)row * N_WIRES + 256 + 8 * lane);
        float4 a0 = xl[0], a1 = xl[1], b0 = xu[0], b1 = xu[1];
        L[0] = pk(a0.x, a1.x); L[1] = pk(a0.y, a1.y);
        L[2] = pk(a0.z, a1.z); L[3] = pk(a0.w, a1.w);
        U[0] = pk(b0.x, b1.x); U[1] = pk(b0.y, b1.y);
        U[2] = pk(b0.z, b1.z); U[3] = pk(b0.w, b1.w);
    }

    __syncthreads();

    if (tid == 0) {
        #pragma unroll
        for (int pc = 0; pc < 3; ++pc) {
            unsigned mb = s2u(&mbar[pc]);
            mbar_expect_tx(mb, CHUNK_B);
            bulk_g2s(s2u(sbuf) + pc * CHUNK_B, g_tab + (size_t)pc * CHUNK_B, CHUNK_B, mb);
        }
    }

    const unsigned sb = s2u(sbuf);
    unsigned rbase = sb + lane * 16;

    CoefH A0, A1, B0, B1;
    int rb = 0;
    #pragma unroll 1
    for (int c = 0; c < NCHUNK; ++c) {
        mbar_wait(s2u(&mbar[rb]), (unsigned)((c / 3) & 1));

        if (c >= MID_LO && c <= MID_HI) {
            LDB(A0, B0, 0);
            LDB(A1, B1, 1);   stage_both(L, U, A0, B0, lane, idxn, idxp);
            LDB(A0, B0, 2);   stage_both(L, U, A1, B1, lane, idxn, idxp);
            LDB(A1, B1, 3);   stage_both(L, U, A0, B0, lane, idxn, idxp);
            LDB(A0, B0, 4);   stage_both(L, U, A1, B1, lane, idxn, idxp);
            LDB(A1, B1, 5);   stage_both(L, U, A0, B0, lane, idxn, idxp);
            LDB(A0, B0, 6);   stage_both(L, U, A1, B1, lane, idxn, idxp);
            LDB(A1, B1, 7);   stage_both(L, U, A0, B0, lane, idxn, idxp);
            LDB(A0, B0, 8);   stage_both(L, U, A1, B1, lane, idxn, idxp);
            LDB(A1, B1, 9);   stage_both(L, U, A0, B0, lane, idxn, idxp);
            LDB(A0, B0, 10);  stage_both(L, U, A1, B1, lane, idxn, idxp);
            LDB(A1, B1, 11);  stage_both(L, U, A0, B0, lane, idxn, idxp);
            LDB(A0, B0, 12);  stage_both(L, U, A1, B1, lane, idxn, idxp);
            LDB(A1, B1, 13);  stage_both(L, U, A0, B0, lane, idxn, idxp);
            stage_both(L, U, A1, B1, lane, idxn, idxp);
        } else {
            LDL(A0, 0);
            LDL(A1, 1);    stage_lower(L, A0, lane);
            LDL(A0, 2);    stage_lower(L, A1, lane);
            LDL(A1, 3);    stage_lower(L, A0, lane);
            LDL(A0, 4);    stage_lower(L, A1, lane);
            LDL(A1, 5);    stage_lower(L, A0, lane);
            LDL(A0, 6);    stage_lower(L, A1, lane);
            LDL(A1, 7);    stage_lower(L, A0, lane);
            LDL(A0, 8);    stage_lower(L, A1, lane);
            LDL(A1, 9);    stage_lower(L, A0, lane);
            LDL(A0, 10);   stage_lower(L, A1, lane);
            LDL(A1, 11);   stage_lower(L, A0, lane);
            LDL(A0, 12);   stage_lower(L, A1, lane);
            LDL(A1, 13);   stage_lower(L, A0, lane);
            stage_lower(L, A1, lane);
        }

        __syncthreads();
        if (tid == 0 && c + 3 < NCHUNK) {
            fence_async_shared();
            unsigned mb = s2u(&mbar[rb]);
            mbar_expect_tx(mb, CHUNK_B);
            bulk_g2s(sb + rb * CHUNK_B, g_tab + (size_t)(c + 3) * CHUNK_B, CHUNK_B, mb);
        }

        rb = (rb == 2) ? 0 : rb + 1;
        rbase += CHUNK_B;
        if (rb == 0) rbase -= 3 * CHUNK_B;
    }

    {
        const float* bl = bias + 8 * lane;
        float* ol = out + (size_t)row * N_WIRES + 8 * lane;
        float4 bb0 = *reinterpret_cast<const float4*>(bl);
        float4 bb1 = *reinterpret_cast<const float4*>(bl + 4);
        float4 bb2 = *reinterpret_cast<const float4*>(bl + 256);
        float4 bb3 = *reinterpret_cast<const float4*>(bl + 260);
        float4 o0, o1, o2, o3;
        o0.x = lo_f(L[0]) + bb0.x; o0.y = lo_f(L[1]) + bb0.y;
        o0.z = lo_f(L[2]) + bb0.z; o0.w = lo_f(L[3]) + bb0.w;
        o1.x = hi_f(L[0]) + bb1.x; o1.y = hi_f(L[1]) + bb1.y;
        o1.z = hi_f(L[2]) + bb1.z; o1.w = hi_f(L[3]) + bb1.w;
        o2.x = lo_f(U[0]) + bb2.x; o2.y = lo_f(U[1]) + bb2.y;
        o2.z = lo_f(U[2]) + bb2.z; o2.w = lo_f(U[3]) + bb2.w;
        o3.x = hi_f(U[0]) + bb3.x; o3.y = hi_f(U[1]) + bb3.y;
        o3.z = hi_f(U[2]) + bb3.z; o3.w = hi_f(U[3]) + bb3.w;
        *reinterpret_cast<float4*>(ol)       = o0;
        *reinterpret_cast<float4*>(ol + 4)   = o1;
        *reinterpret_cast<float4*>(ol + 256) = o2;
        *reinterpret_cast<float4*>(ol + 260) = o3;
    }
}

extern "C" void kernel_launch(void* const* d_in, const int* in_sizes, int n_in,
                              void* d_out, int out_size) {
    const float* x      = (const float*)d_in[0];
    const float* thetas = (const float*)d_in[1];
    const float* bias   = (const float*)d_in[2];
    float* out = (float*)d_out;

    build_cs_kernel<<<(T_PAD + 3) / 4, 512>>>(thetas);

    cudaFuncSetAttribute(apply_kernel,
                         cudaFuncAttributeMaxDynamicSharedMemorySize, 3 * CHUNK_B);

    int B = in_sizes[0] / N_WIRES;   // 256
    apply_kernel<<<B / 2, 64, 3 * CHUNK_B>>>(x, bias, out);
}